// round 1
// baseline (speedup 1.0000x reference)
#include <cuda_runtime.h>
#include <cuda_fp16.h>
#include <stdint.h>

// Problem shape (fixed by the dataset)
#define B_ 16
#define T_ 51
#define P_ 2048
#define Q_ 2048

// Tiling
#define PC 32                     // p's per main block
#define PSPLIT (P_ / PC)          // 64
#define QT 256                    // q's per main block (1 per thread)
#define QSPLIT (Q_ / QT)          // 8
#define ROWB 48                   // bytes per (p,t) row: 16 halfs (32B) + 16B pad for bank spread
#define SLAB_B (T_ * ROWB)        // 2448 bytes per p
#define SLAB_TOTAL (PC * SLAB_B)  // 78336 bytes of dynamic smem

// Static device scratch (no allocations allowed)
__device__ __align__(16) unsigned char g_pairs[(size_t)P_ * SLAB_B];     // ~5 MB fp16 transposed buf
__device__ float g_partial[(size_t)PSPLIT * B_ * Q_];                    // 8.4 MB partial sums

__device__ __forceinline__ __half2 uint_as_half2(unsigned u) {
    __half2 h;
    *reinterpret_cast<unsigned*>(&h) = u;
    return h;
}

// ---------------------------------------------------------------------------
// Kernel 1: transpose buf [B,T,P] fp32  ->  g_pairs [p][t][b] fp16 (48B rows)
// ---------------------------------------------------------------------------
#define PC_PRE 8
__global__ void prep_kernel(const float* __restrict__ buf) {
    __shared__ float stage[B_][T_][PC_PRE + 1];   // 29376 B
    int p0 = blockIdx.x * PC_PRE;

    for (int idx = threadIdx.x; idx < B_ * T_ * PC_PRE; idx += blockDim.x) {
        int b  = idx / (T_ * PC_PRE);
        int r  = idx % (T_ * PC_PRE);
        int t  = r / PC_PRE;
        int pl = r % PC_PRE;
        stage[b][t][pl] = buf[((size_t)b * T_ + t) * P_ + p0 + pl];
    }
    __syncthreads();

    for (int idx = threadIdx.x; idx < PC_PRE * T_; idx += blockDim.x) {
        int pl = idx / T_;
        int t  = idx % T_;
        unsigned u[8];
#pragma unroll
        for (int k = 0; k < 8; k++) {
            __half2 hh = __floats2half2_rn(stage[2 * k][t][pl], stage[2 * k + 1][t][pl]);
            u[k] = *reinterpret_cast<unsigned*>(&hh);
        }
        unsigned char* dstp = g_pairs + ((size_t)(p0 + pl) * T_ + t) * ROWB;
        *reinterpret_cast<uint4*>(dstp)      = make_uint4(u[0], u[1], u[2], u[3]); // b0..b7
        *reinterpret_cast<uint4*>(dstp + 16) = make_uint4(u[4], u[5], u[6], u[7]); // b8..b15
    }
}

// ---------------------------------------------------------------------------
// Kernel 2: main gather + weighted reduce over a (q-tile, p-chunk)
// ---------------------------------------------------------------------------
__global__ void __launch_bounds__(256, 2)
main_kernel(const float* __restrict__ weight, const float* __restrict__ delay) {
    extern __shared__ unsigned char smem[];
    int qb = blockIdx.x;            // 0..QSPLIT-1
    int pb = blockIdx.y;            // 0..PSPLIT-1
    int q  = qb * QT + threadIdx.x;

    // Copy this p-chunk's slab (contiguous in g_pairs) into shared memory.
    {
        const uint4* src = reinterpret_cast<const uint4*>(g_pairs + (size_t)pb * SLAB_TOTAL);
        uint4* dst = reinterpret_cast<uint4*>(smem);
        for (int i = threadIdx.x; i < SLAB_TOTAL / 16; i += 256) dst[i] = src[i];
    }
    __syncthreads();

    float acc[16];
#pragma unroll
    for (int b = 0; b < 16; b++) acc[b] = 0.0f;

    const float* wp = weight + (size_t)(pb * PC) * Q_ + q;
    const float* dp = delay  + (size_t)(pb * PC) * Q_ + q;
    float w_n = wp[0];
    float d_n = dp[0];

#pragma unroll 4
    for (int pl = 0; pl < PC; pl++) {
        float w = w_n, draw = d_n;
        if (pl + 1 < PC) {                    // prefetch next p's weight/delay (coalesced)
            w_n = wp[(size_t)(pl + 1) * Q_];
            d_n = dp[(size_t)(pl + 1) * Q_];
        }

        // d = D_MAX * sigmoid(draw); s is continuous in d so fast-math floor flips are harmless
        float d   = 50.0f * __fdividef(1.0f, 1.0f + __expf(-draw));
        float fdf = floorf(d);
        int   df  = (int)fdf;
        if (df > 49) { df = 49; fdf = 49.0f; }   // d==50 edge: alpha becomes 1, picks row 50
        float a  = d - fdf;
        float wa = w * a;
        float w1 = w - wa;                       // w * (1 - a)

        const unsigned char* row = smem + pl * SLAB_B + df * ROWB;
        uint4 f0 = *reinterpret_cast<const uint4*>(row);                // tap df,  b0..b7
        uint4 f1 = *reinterpret_cast<const uint4*>(row + 16);           // tap df,  b8..b15
        uint4 c0 = *reinterpret_cast<const uint4*>(row + ROWB);         // tap df+1,b0..b7
        uint4 c1 = *reinterpret_cast<const uint4*>(row + ROWB + 16);    // tap df+1,b8..b15

#define STEP(uf, uc, i0) {                                      \
        float2 sf = __half22float2(uint_as_half2(uf));          \
        float2 sc = __half22float2(uint_as_half2(uc));          \
        acc[i0]     = fmaf(w1, sf.x, fmaf(wa, sc.x, acc[i0]));  \
        acc[i0 + 1] = fmaf(w1, sf.y, fmaf(wa, sc.y, acc[i0 + 1])); }

        STEP(f0.x, c0.x, 0)  STEP(f0.y, c0.y, 2)
        STEP(f0.z, c0.z, 4)  STEP(f0.w, c0.w, 6)
        STEP(f1.x, c1.x, 8)  STEP(f1.y, c1.y, 10)
        STEP(f1.z, c1.z, 12) STEP(f1.w, c1.w, 14)
#undef STEP
    }

    // Write fp32 partials for this p-chunk (coalesced over q).
    float* part = g_partial + (size_t)pb * B_ * Q_ + q;
#pragma unroll
    for (int b = 0; b < 16; b++) part[(size_t)b * Q_] = acc[b];
}

// ---------------------------------------------------------------------------
// Kernel 3: deterministic reduction of p-chunk partials -> out [B, Q]
// ---------------------------------------------------------------------------
__global__ void reduce_kernel(float* __restrict__ out) {
    int i = blockIdx.x * blockDim.x + threadIdx.x;   // 0 .. B_*Q_-1
    float s = 0.0f;
#pragma unroll 8
    for (int c = 0; c < PSPLIT; c++) s += g_partial[(size_t)c * B_ * Q_ + i];
    out[i] = s;
}

// ---------------------------------------------------------------------------
extern "C" void kernel_launch(void* const* d_in, const int* in_sizes, int n_in,
                              void* d_out, int out_size) {
    (void)in_sizes; (void)n_in; (void)out_size;
    const float* buf    = (const float*)d_in[0];
    const float* weight = (const float*)d_in[1];
    const float* delay  = (const float*)d_in[2];

    cudaFuncSetAttribute(main_kernel, cudaFuncAttributeMaxDynamicSharedMemorySize, SLAB_TOTAL);

    prep_kernel<<<P_ / PC_PRE, 256>>>(buf);
    main_kernel<<<dim3(QSPLIT, PSPLIT), 256, SLAB_TOTAL>>>(weight, delay);
    reduce_kernel<<<(B_ * Q_) / 256, 256>>>((float*)d_out);
}

// round 2
// speedup vs baseline: 1.2737x; 1.2737x over previous
#include <cuda_runtime.h>
#include <cuda_fp16.h>
#include <stdint.h>

// Problem shape (fixed by the dataset)
#define B_ 16
#define T_ 51
#define P_ 2048
#define Q_ 2048

// Tiling
#define PC 32                     // p's per main block (== warp size: lane = pl for coalesced loads)
#define PSPLIT (P_ / PC)          // 64
#define QT 256                    // q's per main block (1 per thread)
#define QSPLIT (Q_ / QT)          // 8
#define ROWB 48                   // bytes per (p,t) row: 16 halfs (32B) + 16B pad -> odd 16B-granule stride
#define SLAB_B (T_ * ROWB)        // 2448 bytes per p
#define SLAB_TOTAL (PC * SLAB_B)  // 78336 bytes of dynamic smem

// Static device scratch (no allocations allowed)
__device__ float g_partial[(size_t)PSPLIT * B_ * Q_];   // 8.4 MB partial sums

__device__ __forceinline__ __half2 uint_as_half2(unsigned u) {
    __half2 h;
    *reinterpret_cast<unsigned*>(&h) = u;
    return h;
}

// ---------------------------------------------------------------------------
// Main kernel: in-block transpose buf[B,T,pchunk] -> fp16 slab, then gather +
// weighted reduce over a (q-tile, p-chunk).
// ---------------------------------------------------------------------------
__global__ void __launch_bounds__(256, 2)
main_kernel(const float* __restrict__ buf,
            const float* __restrict__ weight,
            const float* __restrict__ delay) {
    extern __shared__ unsigned char smem[];
    const int qb = blockIdx.x;            // 0..QSPLIT-1
    const int pb = blockIdx.y;            // 0..PSPLIT-1
    const int q  = qb * QT + threadIdx.x;
    const int p0 = pb * PC;

    // ---- Phase 1: build fp16 slab [pl][t][b] directly from buf ----
    // Work item = (t, o): o selects b-octet (b = 8o..8o+7). lane = pl.
    // LDG: 8 coalesced 128B loads per item. STS.128 at granule pl*153+3t+o:
    // superbank (pl+3t+o) mod 8 -> exact 4-way = crossbar floor.
    {
        const int lane = threadIdx.x & 31;
        const int warp = threadIdx.x >> 5;
        for (int item = warp; item < T_ * 2; item += 8) {
            const int t = item >> 1;
            const int o = item & 1;
            const float* src = buf + (size_t)(8 * o) * T_ * P_ + (size_t)t * P_ + p0 + lane;
            unsigned u[4];
#pragma unroll
            for (int k = 0; k < 4; k++) {
                float lo = src[(size_t)(2 * k)     * T_ * P_];
                float hi = src[(size_t)(2 * k + 1) * T_ * P_];
                __half2 hh = __floats2half2_rn(lo, hi);
                u[k] = *reinterpret_cast<unsigned*>(&hh);
            }
            *reinterpret_cast<uint4*>(smem + lane * SLAB_B + t * ROWB + o * 16) =
                make_uint4(u[0], u[1], u[2], u[3]);
        }
    }
    __syncthreads();

    // ---- Phase 2: gather + accumulate ----
    float acc[16];
#pragma unroll
    for (int b = 0; b < 16; b++) acc[b] = 0.0f;

    const float* wp = weight + (size_t)p0 * Q_ + q;
    const float* dp = delay  + (size_t)p0 * Q_ + q;
    float w_n = wp[0];
    float d_n = dp[0];

#pragma unroll 4
    for (int pl = 0; pl < PC; pl++) {
        float w = w_n, draw = d_n;
        if (pl + 1 < PC) {                    // prefetch next p's weight/delay (coalesced)
            w_n = wp[(size_t)(pl + 1) * Q_];
            d_n = dp[(size_t)(pl + 1) * Q_];
        }

        // d = D_MAX * sigmoid(draw); s is continuous in d so fast-math floor flips are harmless
        float d   = 50.0f * __fdividef(1.0f, 1.0f + __expf(-draw));
        float fdf = floorf(d);
        int   df  = (int)fdf;
        if (df > 49) { df = 49; fdf = 49.0f; }   // d==50 edge: alpha -> 1, picks row 50
        float a  = d - fdf;
        float wa = w * a;
        float w1 = w - wa;                       // w * (1 - a)

        const unsigned char* row = smem + pl * SLAB_B + df * ROWB;
        uint4 f0 = *reinterpret_cast<const uint4*>(row);                // tap df,   b0..b7
        uint4 f1 = *reinterpret_cast<const uint4*>(row + 16);           // tap df,   b8..b15
        uint4 c0 = *reinterpret_cast<const uint4*>(row + ROWB);         // tap df+1, b0..b7
        uint4 c1 = *reinterpret_cast<const uint4*>(row + ROWB + 16);    // tap df+1, b8..b15

#define STEP(uf, uc, i0) {                                      \
        float2 sf = __half22float2(uint_as_half2(uf));          \
        float2 sc = __half22float2(uint_as_half2(uc));          \
        acc[i0]     = fmaf(w1, sf.x, fmaf(wa, sc.x, acc[i0]));  \
        acc[i0 + 1] = fmaf(w1, sf.y, fmaf(wa, sc.y, acc[i0 + 1])); }

        STEP(f0.x, c0.x, 0)  STEP(f0.y, c0.y, 2)
        STEP(f0.z, c0.z, 4)  STEP(f0.w, c0.w, 6)
        STEP(f1.x, c1.x, 8)  STEP(f1.y, c1.y, 10)
        STEP(f1.z, c1.z, 12) STEP(f1.w, c1.w, 14)
#undef STEP
    }

    // Write fp32 partials for this p-chunk (coalesced over q).
    float* part = g_partial + (size_t)pb * B_ * Q_ + q;
#pragma unroll
    for (int b = 0; b < 16; b++) part[(size_t)b * Q_] = acc[b];
}

// ---------------------------------------------------------------------------
// Deterministic reduction of p-chunk partials -> out [B, Q]
// ---------------------------------------------------------------------------
__global__ void reduce_kernel(float* __restrict__ out) {
    int i = blockIdx.x * blockDim.x + threadIdx.x;   // 0 .. B_*Q_-1
    float s = 0.0f;
#pragma unroll 8
    for (int c = 0; c < PSPLIT; c++) s += g_partial[(size_t)c * B_ * Q_ + i];
    out[i] = s;
}

// ---------------------------------------------------------------------------
extern "C" void kernel_launch(void* const* d_in, const int* in_sizes, int n_in,
                              void* d_out, int out_size) {
    (void)in_sizes; (void)n_in; (void)out_size;
    const float* buf    = (const float*)d_in[0];
    const float* weight = (const float*)d_in[1];
    const float* delay  = (const float*)d_in[2];

    cudaFuncSetAttribute(main_kernel, cudaFuncAttributeMaxDynamicSharedMemorySize, SLAB_TOTAL);

    main_kernel<<<dim3(QSPLIT, PSPLIT), QT, SLAB_TOTAL>>>(buf, weight, delay);
    reduce_kernel<<<(B_ * Q_) / 256, 256>>>((float*)d_out);
}

// round 5
// speedup vs baseline: 1.4110x; 1.1078x over previous
#include <cuda_runtime.h>
#include <cuda_fp16.h>
#include <stdint.h>

// Problem shape (fixed by the dataset)
#define B_ 16
#define T_ 51
#define P_ 2048
#define Q_ 2048

// Tiling
#define PC 32                     // p's per slab (== warp size: lane = pl for coalesced loads)
#define NP 2                      // p-chunks accumulated per block (halves partial traffic)
#define PSPLIT (P_ / (PC * NP))   // 32 partial slices
#define QT 256                    // q's per main block (1 per thread)
#define QSPLIT (Q_ / QT)          // 8
#define ROWB 48                   // bytes per (p,t) row: 16 halfs (32B) + 16B pad -> odd granule stride
#define SLAB_B (T_ * ROWB)        // 2448 bytes per p
#define SLAB_TOTAL (PC * SLAB_B)  // 78336 bytes of dynamic smem

#define BQ (B_ * Q_)              // 32768 outputs
#define RSLICE 4                  // reduce stage-A slices
#define RCHUNK (PSPLIT / RSLICE)  // 8 chunks per slice

// Static device scratch (no allocations allowed)
__device__ float g_partial[(size_t)PSPLIT * BQ];    // 4.2 MB
__device__ float g_partial2[(size_t)RSLICE * BQ];   // 0.5 MB

__device__ __forceinline__ __half2 uint_as_half2(unsigned u) {
    __half2 h;
    *reinterpret_cast<unsigned*>(&h) = u;
    return h;
}

// ---------------------------------------------------------------------------
// Main kernel: for NP p-chunks, build fp16 slab in-block from buf, gather +
// weighted-accumulate; one partial write per block.
// ---------------------------------------------------------------------------
__global__ void __launch_bounds__(256, 2)
main_kernel(const float* __restrict__ buf,
            const float* __restrict__ weight,
            const float* __restrict__ delay) {
    extern __shared__ unsigned char smem[];
    const int qb  = blockIdx.x;           // 0..QSPLIT-1
    const int pb2 = blockIdx.y;           // 0..PSPLIT-1
    const int q   = qb * QT + threadIdx.x;

    float acc[16];
#pragma unroll
    for (int b = 0; b < 16; b++) acc[b] = 0.0f;

    for (int c = 0; c < NP; c++) {
        const int p0 = (pb2 * NP + c) * PC;
        if (c) __syncthreads();           // everyone done reading previous slab

        // ---- Phase 1: build fp16 slab [pl][t][b] directly from buf ----
        // lane = pl -> coalesced 128B LDG per (b,t); STS.128 granule
        // pl*153 + 3t + o -> superbank (pl+3t+o) mod 8 = exact 4-way (floor).
        {
            const int lane = threadIdx.x & 31;
            const int warp = threadIdx.x >> 5;
            for (int item = warp; item < T_ * 2; item += 8) {
                const int t = item >> 1;
                const int o = item & 1;
                const float* src = buf + (size_t)(8 * o) * T_ * P_ + (size_t)t * P_ + p0 + lane;
                unsigned u[4];
#pragma unroll
                for (int k = 0; k < 4; k++) {
                    float lo = src[(size_t)(2 * k)     * T_ * P_];
                    float hi = src[(size_t)(2 * k + 1) * T_ * P_];
                    __half2 hh = __floats2half2_rn(lo, hi);
                    u[k] = *reinterpret_cast<unsigned*>(&hh);
                }
                *reinterpret_cast<uint4*>(smem + lane * SLAB_B + t * ROWB + o * 16) =
                    make_uint4(u[0], u[1], u[2], u[3]);
            }
        }
        __syncthreads();

        // ---- Phase 2: gather + accumulate ----
        const float* wp = weight + (size_t)p0 * Q_ + q;
        const float* dp = delay  + (size_t)p0 * Q_ + q;
        float w_n = wp[0];
        float d_n = dp[0];

#pragma unroll 4
        for (int pl = 0; pl < PC; pl++) {
            float w = w_n, draw = d_n;
            if (pl + 1 < PC) {                 // prefetch next p's weight/delay (coalesced)
                w_n = wp[(size_t)(pl + 1) * Q_];
                d_n = dp[(size_t)(pl + 1) * Q_];
            }

            // d = D_MAX * sigmoid(draw); s is continuous in d so fast-math flips are harmless
            float d   = 50.0f * __fdividef(1.0f, 1.0f + __expf(-draw));
            float fdf = floorf(d);
            int   df  = (int)fdf;
            if (df > 49) { df = 49; fdf = 49.0f; }   // d==50 edge: alpha -> 1, picks row 50
            float a  = d - fdf;
            float wa = w * a;
            float w1 = w - wa;                       // w * (1 - a)

            const unsigned char* row = smem + pl * SLAB_B + df * ROWB;
            uint4 f0 = *reinterpret_cast<const uint4*>(row);                // df,   b0..b7
            uint4 f1 = *reinterpret_cast<const uint4*>(row + 16);           // df,   b8..b15
            uint4 c0 = *reinterpret_cast<const uint4*>(row + ROWB);         // df+1, b0..b7
            uint4 c1 = *reinterpret_cast<const uint4*>(row + ROWB + 16);    // df+1, b8..b15

#define STEP(uf, uc, i0) {                                      \
            float2 sf = __half22float2(uint_as_half2(uf));      \
            float2 sc = __half22float2(uint_as_half2(uc));      \
            acc[i0]     = fmaf(w1, sf.x, fmaf(wa, sc.x, acc[i0]));  \
            acc[i0 + 1] = fmaf(w1, sf.y, fmaf(wa, sc.y, acc[i0 + 1])); }

            STEP(f0.x, c0.x, 0)  STEP(f0.y, c0.y, 2)
            STEP(f0.z, c0.z, 4)  STEP(f0.w, c0.w, 6)
            STEP(f1.x, c1.x, 8)  STEP(f1.y, c1.y, 10)
            STEP(f1.z, c1.z, 12) STEP(f1.w, c1.w, 14)
#undef STEP
        }
    }

    // Write fp32 partials for this p-chunk pair (coalesced over q).
    float* part = g_partial + (size_t)pb2 * BQ + q;
#pragma unroll
    for (int b = 0; b < 16; b++) part[(size_t)b * Q_] = acc[b];
}

// ---------------------------------------------------------------------------
// Deterministic two-stage reduction of partials -> out [B, Q]
// ---------------------------------------------------------------------------
__global__ void reduceA_kernel() {
    int i = blockIdx.x * blockDim.x + threadIdx.x;   // 0 .. BQ-1
    const float* src = g_partial + (size_t)(blockIdx.y * RCHUNK) * BQ + i;
    float s = 0.0f;
#pragma unroll
    for (int k = 0; k < RCHUNK; k++) s += src[(size_t)k * BQ];
    g_partial2[(size_t)blockIdx.y * BQ + i] = s;
}

__global__ void reduceB_kernel(float* __restrict__ out) {
    int i = blockIdx.x * blockDim.x + threadIdx.x;   // 0 .. BQ-1
    float s = 0.0f;
#pragma unroll
    for (int c = 0; c < RSLICE; c++) s += g_partial2[(size_t)c * BQ + i];
    out[i] = s;
}

// ---------------------------------------------------------------------------
extern "C" void kernel_launch(void* const* d_in, const int* in_sizes, int n_in,
                              void* d_out, int out_size) {
    (void)in_sizes; (void)n_in; (void)out_size;
    const float* buf    = (const float*)d_in[0];
    const float* weight = (const float*)d_in[1];
    const float* delay  = (const float*)d_in[2];

    cudaFuncSetAttribute(main_kernel, cudaFuncAttributeMaxDynamicSharedMemorySize, SLAB_TOTAL);

    main_kernel<<<dim3(QSPLIT, PSPLIT), QT, SLAB_TOTAL>>>(buf, weight, delay);
    reduceA_kernel<<<dim3(BQ / 128, RSLICE), 128>>>();   // 1024 blocks: spread across all SMs
    reduceB_kernel<<<BQ / 256, 256>>>((float*)d_out);
}